// round 2
// baseline (speedup 1.0000x reference)
#include <cuda_runtime.h>

#define NODES 62
#define BATCHG 2048
#define NN (NODES*BATCHG)          // 126976
#define HROW 384                   // x:0-128, x1:128-192, x2:192-256, x3:256-320, x4:320-384
#define PCOLS 192                  // P: c0 [0,64), c1 [64,128), c2 [128,192)  (62 real cols each)
#define LINW 512
#define LIN2 256
#define FEATK (62*256)             // 15872 padded feats K
#define EPB 496                    // edges of graph 0
#define KSPLIT 8

// ---------------- scratch (static device arrays; no allocation) ----------------
__device__ float g_H[(size_t)NN*HROW];        // layer feature buffer, 195MB
__device__ float g_P[(size_t)NN*PCOLS];       // cheb GEMM output,     97MB
__device__ float g_Wp[4][320*192];            // prepped cheb weights
__device__ float g_Wh1p[(size_t)FEATK*LINW];  // padded Wh1, 32.5MB
__device__ float g_G1p[(size_t)KSPLIT*BATCHG*LINW]; // split-K partials
__device__ float g_G1[BATCHG*LINW];
__device__ float g_G2[BATCHG*LIN2];
__device__ float g_L[62*64];
__device__ float g_L2[62*64];
__device__ float g_deg[64];
__device__ float g_mean[LINW];
__device__ float g_rstd[LINW];

// ---------------- init: H[:,0:128] = x, rest = 0 ----------------
__global__ void k_init_H(const float* __restrict__ x) {
    size_t idx = (size_t)blockIdx.x * blockDim.x + threadIdx.x;
    size_t total = (size_t)NN * (HROW/4);
    if (idx >= total) return;
    size_t n = idx / (HROW/4);
    int c4 = (int)(idx % (HROW/4));
    float4 v = make_float4(0.f,0.f,0.f,0.f);
    if (c4 < 32) v = reinterpret_cast<const float4*>(x)[n*32 + c4];
    reinterpret_cast<float4*>(g_H)[idx] = v;
}

// ---------------- build L (graph 0 topology == all graphs) ----------------
__global__ void k_deg(const int* __restrict__ row) {
    int t = threadIdx.x;
    if (t < 64) g_deg[t] = 0.f;
    __syncthreads();
    if (t < EPB) atomicAdd(&g_deg[row[t]], 1.0f);
}

__global__ void k_build_L(const int* __restrict__ row, const int* __restrict__ col) {
    int t = threadIdx.x;
    for (int i = t; i < 62*64; i += 512) { g_L[i] = 0.f; g_L2[i] = 0.f; }
    __syncthreads();
    if (t < EPB) {
        int r = row[t], c = col[t];
        float w = -rsqrtf(g_deg[r]) * rsqrtf(g_deg[c]);
        atomicAdd(&g_L[r*64 + c], w);   // equal-valued adds -> deterministic
    }
}

__global__ void k_L2() {
    int t = blockIdx.x*256 + threadIdx.x;
    if (t >= 62*64) return;
    int i = t / 64, j = t % 64;
    float s = 0.f;
    if (j < 62)
        for (int m = 0; m < 62; m++) s += g_L[i*64+m] * g_L[m*64+j];
    g_L2[t] = s;
}

// ---------------- weight prep ----------------
// Wp[dpad][192]: cols [0,62)=W0-W2, [64,126)=W1, [128,190)=2*W2, pads zero.
// padded row r -> real feature row rr (x:0-127 direct; chunks of 64 -> 62 real).
__global__ void k_prepW(const float* __restrict__ W, int dreal, int dpad,
                        float* __restrict__ Wp) {
    int t = blockIdx.x*256 + threadIdx.x;
    if (t >= dpad*192) return;
    int r = t / 192, c = t % 192;
    int ch = c >> 6, j = c & 63;
    float val = 0.f;
    int rr = -1;
    if (r < 128) rr = r;
    else { int q = r - 128; int chunk = q >> 6, w = q & 63; if (w < 62) rr = 128 + chunk*62 + w; }
    if (rr >= 0 && rr < dreal && j < 62) {
        const float* W0 = W;
        const float* W1 = W + (size_t)dreal*62;
        const float* W2 = W + (size_t)2*dreal*62;
        if (ch == 0)      val = W0[rr*62+j] - W2[rr*62+j];
        else if (ch == 1) val = W1[rr*62+j];
        else              val = 2.f * W2[rr*62+j];
    }
    Wp[t] = val;
}

// Wh1p[15872][512] from Wh1[15376][512]: padded k -> (node, chunk, w)
__global__ void k_prepWh1(const float* __restrict__ Wh1) {
    int t = blockIdx.x*256 + threadIdx.x;
    if (t >= FEATK*LINW) return;
    int r = t / LINW, c = t % LINW;
    int node = r >> 8, cc = r & 255;
    int ch = cc >> 6, w = cc & 63;
    float val = 0.f;
    if (w < 62) val = Wh1[((size_t)(node*248 + ch*62 + w))*LINW + c];
    g_Wh1p[t] = val;
}

// ---------------- generic fp32 GEMM: 64x64 tile, BK=16, 256 thr, 4x4/thread ----------
// FEATS mode: A element (m,k) read from g_H viewed as [2048, 62*384] with
// offset (k>>8)*384 + 128 + (k&255)  (reads feats in place, pads are zero).
template<bool FEATS>
__global__ void gemm_k(const float* __restrict__ A, const float* __restrict__ B,
                       float* __restrict__ C, int M, int N, int K,
                       int lda, int ldb, int ldc, int kparts, size_t cstride)
{
    __shared__ float As[16][68];
    __shared__ float Bs[16][64];
    int t = threadIdx.x;
    int m0 = blockIdx.y * 64, n0 = blockIdx.x * 64;
    int kper = K / kparts;
    int kbeg = blockIdx.z * kper, kend = kbeg + kper;
    float* Cz = C + (size_t)blockIdx.z * cstride;
    int ty = t >> 4, tx = t & 15;
    int am = t >> 2, ak = (t & 3) * 4;
    int bk = t >> 4, bn = (t & 15) * 4;
    float acc[4][4];
#pragma unroll
    for (int i = 0; i < 4; i++)
#pragma unroll
        for (int j = 0; j < 4; j++) acc[i][j] = 0.f;

    for (int k0 = kbeg; k0 < kend; k0 += 16) {
        size_t aoff;
        if (FEATS) {
            int kk = k0 + ak;
            aoff = (size_t)(m0+am)*23808 + (size_t)((kk >> 8)*384 + 128 + (kk & 255));
        } else {
            aoff = (size_t)(m0+am)*lda + (k0 + ak);
        }
        float4 av = *reinterpret_cast<const float4*>(A + aoff);
        As[ak+0][am] = av.x; As[ak+1][am] = av.y; As[ak+2][am] = av.z; As[ak+3][am] = av.w;
        float4 bv = *reinterpret_cast<const float4*>(B + (size_t)(k0+bk)*ldb + n0 + bn);
        *reinterpret_cast<float4*>(&Bs[bk][bn]) = bv;
        __syncthreads();
#pragma unroll
        for (int k = 0; k < 16; k++) {
            float4 a4 = *reinterpret_cast<const float4*>(&As[k][ty*4]);
            float4 b4 = *reinterpret_cast<const float4*>(&Bs[k][tx*4]);
            float a[4] = {a4.x, a4.y, a4.z, a4.w};
            float b[4] = {b4.x, b4.y, b4.z, b4.w};
#pragma unroll
            for (int i = 0; i < 4; i++)
#pragma unroll
                for (int j = 0; j < 4; j++) acc[i][j] += a[i]*b[j];
        }
        __syncthreads();
    }
#pragma unroll
    for (int i = 0; i < 4; i++) {
        float4 v = make_float4(acc[i][0], acc[i][1], acc[i][2], acc[i][3]);
        *reinterpret_cast<float4*>(Cz + (size_t)(m0 + ty*4 + i)*ldc + n0 + tx*4) = v;
    }
}

__global__ void k_reduceK() {
    int t = blockIdx.x*256 + threadIdx.x;
    if (t >= BATCHG*LINW) return;
    float s = 0.f;
#pragma unroll
    for (int p = 0; p < KSPLIT; p++) s += g_G1p[(size_t)p*BATCHG*LINW + t];
    g_G1[t] = s;
}

// ---------------- combine: out = P0 + L@P1 + L2@P2, +bias, relu -> H chunk ----------
__global__ void k_combine(const float* __restrict__ bias, int cbase) {
    __shared__ float Ps[62][192];
    int b = blockIdx.x;
    int t = threadIdx.x;
    const float* Pg = g_P + (size_t)b * 62 * 192;
    for (int idx = t; idx < 62*48; idx += 256) {
        int m = idx / 48, q = idx % 48;
        *reinterpret_cast<float4*>(&Ps[m][q*4]) =
            *reinterpret_cast<const float4*>(Pg + m*192 + q*4);
    }
    __syncthreads();
    int j4 = t & 15;  int jj = j4 * 4;
    int i0 = t >> 4;
    float* Hb = g_H + (size_t)b * 62 * HROW + cbase;
    for (int ii = 0; ii < 4; ii++) {
        int i = i0 + ii*16;
        if (i >= 62) break;
        float4 acc = *reinterpret_cast<float4*>(&Ps[i][jj]);   // identity term (c0)
#pragma unroll 2
        for (int m = 0; m < 62; m++) {
            float l1 = __ldg(&g_L [i*64 + m]);
            float l2 = __ldg(&g_L2[i*64 + m]);
            float4 p1 = *reinterpret_cast<float4*>(&Ps[m][ 64 + jj]);
            float4 p2 = *reinterpret_cast<float4*>(&Ps[m][128 + jj]);
            acc.x += l1*p1.x + l2*p2.x;
            acc.y += l1*p1.y + l2*p2.y;
            acc.z += l1*p1.z + l2*p2.z;
            acc.w += l1*p1.w + l2*p2.w;
        }
        float4 o;
        o.x = (jj+0 < 62) ? fmaxf(acc.x + bias[jj+0], 0.f) : 0.f;
        o.y = (jj+1 < 62) ? fmaxf(acc.y + bias[jj+1], 0.f) : 0.f;
        o.z = (jj+2 < 62) ? fmaxf(acc.z + bias[jj+2], 0.f) : 0.f;
        o.w = (jj+3 < 62) ? fmaxf(acc.w + bias[jj+3], 0.f) : 0.f;
        *reinterpret_cast<float4*>(Hb + (size_t)i*HROW + jj) = o;
    }
}

// ---------------- batchnorm ----------------
__global__ void k_bnstats(const float* __restrict__ X, int ld) {
    int c = blockIdx.x;
    int t = threadIdx.x;
    float s = 0.f, sq = 0.f;
    for (int r = t; r < BATCHG; r += 256) {
        float v = X[(size_t)r*ld + c];
        s += v; sq += v*v;
    }
    __shared__ float sh[256], sh2[256];
    sh[t] = s; sh2[t] = sq; __syncthreads();
    for (int o = 128; o > 0; o >>= 1) {
        if (t < o) { sh[t] += sh[t+o]; sh2[t] += sh2[t+o]; }
        __syncthreads();
    }
    if (t == 0) {
        float m = sh[0] * (1.f/BATCHG);
        float v = sh2[0] * (1.f/BATCHG) - m*m;
        g_mean[c] = m;
        g_rstd[c] = rsqrtf(v + 1e-5f);
    }
}

__global__ void k_bnrelu(float* __restrict__ X, int nc,
                         const float* __restrict__ gamma, const float* __restrict__ beta) {
    int idx = blockIdx.x*256 + threadIdx.x;
    if (idx >= BATCHG*nc) return;
    int c = idx % nc;
    float v = X[idx];
    v = (v - g_mean[c]) * g_rstd[c] * gamma[c] + beta[c];
    X[idx] = fmaxf(v, 0.f);
}

// ---------------- final logits + softmax ----------------
__global__ void k_final(const float* __restrict__ Wh3, const float* __restrict__ bh3,
                        float* __restrict__ out) {
    int r = blockIdx.x*256 + threadIdx.x;
    if (r >= BATCHG) return;
    const float* h = g_G2 + (size_t)r * LIN2;
    float a0 = bh3[0], a1 = bh3[1], a2 = bh3[2];
    for (int k = 0; k < LIN2; k++) {
        float v = h[k];
        a0 += v * Wh3[k*3+0];
        a1 += v * Wh3[k*3+1];
        a2 += v * Wh3[k*3+2];
    }
    float mx = fmaxf(a0, fmaxf(a1, a2));
    float e0 = expf(a0-mx), e1 = expf(a1-mx), e2 = expf(a2-mx);
    float inv = 1.f / (e0+e1+e2);
    out[r*3+0] = e0*inv; out[r*3+1] = e1*inv; out[r*3+2] = e2*inv;
}

// ---------------- launch ----------------
extern "C" void kernel_launch(void* const* d_in, const int* in_sizes, int n_in,
                              void* d_out, int out_size) {
    const float* x   = (const float*)d_in[0];
    const int*   ei  = (const int*)  d_in[1];
    const float* W[4]  = {(const float*)d_in[2], (const float*)d_in[4],
                          (const float*)d_in[6], (const float*)d_in[8]};
    const float* bb[4] = {(const float*)d_in[3], (const float*)d_in[5],
                          (const float*)d_in[7], (const float*)d_in[9]};
    const float* Wh1 = (const float*)d_in[10];
    const float* g1  = (const float*)d_in[12];
    const float* be1 = (const float*)d_in[13];
    const float* Wh2 = (const float*)d_in[14];
    const float* g2  = (const float*)d_in[16];
    const float* be2 = (const float*)d_in[17];
    const float* Wh3 = (const float*)d_in[18];
    const float* bh3 = (const float*)d_in[19];
    float* out = (float*)d_out;

    int E = in_sizes[1] / 2;
    const int* row = ei;
    const int* col = ei + E;

    float *hH, *hP, *hWp, *hWh1p, *hG1p, *hG1, *hG2;
    cudaGetSymbolAddress((void**)&hH,    g_H);
    cudaGetSymbolAddress((void**)&hP,    g_P);
    cudaGetSymbolAddress((void**)&hWp,   g_Wp);
    cudaGetSymbolAddress((void**)&hWh1p, g_Wh1p);
    cudaGetSymbolAddress((void**)&hG1p,  g_G1p);
    cudaGetSymbolAddress((void**)&hG1,   g_G1);
    cudaGetSymbolAddress((void**)&hG2,   g_G2);

    const int DPAD[4]  = {128, 192, 256, 320};
    const int DREAL[4] = {128, 190, 252, 314};

    // init + L
    {
        size_t total = (size_t)NN * (HROW/4);
        k_init_H<<<(unsigned)((total + 255)/256), 256>>>(x);
    }
    k_deg<<<1, 512>>>(row);
    k_build_L<<<1, 512>>>(row, col);
    k_L2<<<16, 256>>>();

    // weight prep
    for (int i = 0; i < 4; i++) {
        int n = DPAD[i]*192;
        k_prepW<<<(n+255)/256, 256>>>(W[i], DREAL[i], DPAD[i], hWp + (size_t)i*320*192);
    }
    k_prepWh1<<<(FEATK*LINW + 255)/256, 256>>>(Wh1);

    // 4 cheb layers
    for (int i = 0; i < 4; i++) {
        gemm_k<false><<<dim3(3, NN/64, 1), 256>>>(
            hH, hWp + (size_t)i*320*192, hP,
            NN, 192, DPAD[i], HROW, 192, 192, 1, 0);
        k_combine<<<BATCHG, 256>>>(bb[i], 128 + 64*i);
    }

    // MLP head
    gemm_k<true><<<dim3(LINW/64, BATCHG/64, KSPLIT), 256>>>(
        hH, hWh1p, hG1p,
        BATCHG, LINW, FEATK, 0, LINW, LINW, KSPLIT, (size_t)BATCHG*LINW);
    k_reduceK<<<(BATCHG*LINW + 255)/256, 256>>>();
    k_bnstats<<<LINW, 256>>>(hG1, LINW);
    k_bnrelu<<<(BATCHG*LINW + 255)/256, 256>>>(hG1, LINW, g1, be1);

    gemm_k<false><<<dim3(LIN2/64, BATCHG/64, 1), 256>>>(
        hG1, Wh2, hG2, BATCHG, LIN2, LINW, LINW, LIN2, LIN2, 1, 0);
    k_bnstats<<<LIN2, 256>>>(hG2, LIN2);
    k_bnrelu<<<(BATCHG*LIN2 + 255)/256, 256>>>(hG2, LIN2, g2, be2);

    k_final<<<(BATCHG + 255)/256, 256>>>(Wh3, bh3, out);
}

// round 4
// speedup vs baseline: 1.2916x; 1.2916x over previous
#include <cuda_runtime.h>
#include <cuda_bf16.h>

typedef unsigned short u16;
typedef unsigned int   u32;
typedef unsigned long long u64;

#define NODES 62
#define BATCHG 2048
#define NN (NODES*BATCHG)          // 126976
#define HROW 384                   // x:0-128 | x1:128-192 | x2:192-256 | x3:256-320 | x4:320-384
#define LINW 512
#define LIN2 256
#define KSPLIT 4
#define EPB 496

// ---------------- static device scratch ----------------
__device__ u16 g_Hh[(size_t)NN*HROW];          // H hi bf16 (97MB)
__device__ u16 g_Hl[(size_t)NN*HROW];          // H lo bf16
__device__ u16 g_Wt_hi[4][5*192*64];           // cheb weights, transposed [blk][n][64]
__device__ u16 g_Wt_lo[4][5*192*64];
__device__ u16 g_Wh1t_hi[(size_t)248*512*64];  // Wh1 transposed blocks
__device__ u16 g_Wh1t_lo[(size_t)248*512*64];
__device__ float g_G1p[(size_t)KSPLIT*BATCHG*LINW];
__device__ float g_G1[BATCHG*LINW];
__device__ float g_G2[BATCHG*LIN2];
__device__ float g_L[62*64];
__device__ float g_L2[62*64];
__device__ float g_deg[64];
__device__ float g_mean[LINW];
__device__ float g_rstd[LINW];

// ---------------- helpers ----------------
__device__ __forceinline__ u32 smem_u32(const void* p){
    u32 a;
    asm("{ .reg .u64 t; cvta.to.shared.u64 t, %1; cvt.u32.u64 %0, t; }" : "=r"(a) : "l"(p));
    return a;
}
__device__ __forceinline__ void ldsm4(u32& r0,u32& r1,u32& r2,u32& r3,u32 addr){
    asm volatile("ldmatrix.sync.aligned.m8n8.x4.shared.b16 {%0,%1,%2,%3}, [%4];"
        : "=r"(r0),"=r"(r1),"=r"(r2),"=r"(r3) : "r"(addr));
}
__device__ __forceinline__ void mma_bf16(float* d, const u32* a, const u32* b){
    asm volatile("mma.sync.aligned.m16n8k16.row.col.f32.bf16.bf16.f32 "
        "{%0,%1,%2,%3}, {%4,%5,%6,%7}, {%8,%9}, {%0,%1,%2,%3};"
        : "+f"(d[0]),"+f"(d[1]),"+f"(d[2]),"+f"(d[3])
        : "r"(a[0]),"r"(a[1]),"r"(a[2]),"r"(a[3]), "r"(b[0]),"r"(b[1]));
}
__device__ __forceinline__ u32 swz(u32 bo){ return bo ^ ((bo >> 3) & 0x70); }
__device__ __forceinline__ void splitbf(float v, u16& h, u16& l){
    __nv_bfloat16 bh = __float2bfloat16(v);
    __nv_bfloat16 bl = __float2bfloat16(v - __bfloat162float(bh));
    h = *reinterpret_cast<u16*>(&bh);
    l = *reinterpret_cast<u16*>(&bl);
}

// ---------------- init: H[:,0:128] = split(x) ----------------
__global__ void k_init_H(const float* __restrict__ x){
    size_t idx = (size_t)blockIdx.x*256 + threadIdx.x;
    if (idx >= (size_t)NN*16) return;
    size_t r = idx >> 4;
    int c8 = ((int)idx & 15) * 8;
    float4 a = *(const float4*)(x + r*128 + c8);
    float4 b = *(const float4*)(x + r*128 + c8 + 4);
    float v[8] = {a.x,a.y,a.z,a.w,b.x,b.y,b.z,b.w};
    union { u16 u[8]; uint4 q; } H, L;
#pragma unroll
    for (int i = 0; i < 8; i++) splitbf(v[i], H.u[i], L.u[i]);
    *(uint4*)(g_Hh + r*HROW + c8) = H.q;
    *(uint4*)(g_Hl + r*HROW + c8) = L.q;
}

// ---------------- graph Laplacian (graph 0 == all graphs) ----------------
__global__ void k_deg(const int* __restrict__ row){
    int t = threadIdx.x;
    if (t < 64) g_deg[t] = 0.f;
    __syncthreads();
    if (t < EPB) atomicAdd(&g_deg[row[t]], 1.0f);
}
__global__ void k_build_L(const int* __restrict__ row, const int* __restrict__ col){
    int t = threadIdx.x;
    for (int i = t; i < 62*64; i += 512) { g_L[i] = 0.f; g_L2[i] = 0.f; }
    __syncthreads();
    if (t < EPB) {
        int r = row[t], c = col[t];
        float w = -rsqrtf(g_deg[r]) * rsqrtf(g_deg[c]);
        atomicAdd(&g_L[r*64 + c], w);
    }
}
__global__ void k_L2(){
    int t = blockIdx.x*256 + threadIdx.x;
    if (t >= 62*64) return;
    int i = t / 64, j = t % 64;
    float s = 0.f;
    if (j < 62)
        for (int m = 0; m < 62; m++) s += g_L[i*64+m] * g_L[m*64+j];
    g_L2[t] = s;
}

// ---------------- weight prep (transposed + bf16 split) ----------------
__global__ void k_prepWt(const float* __restrict__ W, int dreal, int dpad, int layer){
    int t = blockIdx.x*256 + threadIdx.x;
    if (t >= dpad*192) return;
    int n = t % 192, k = t / 192;
    int ch = n >> 6, j = n & 63;
    float val = 0.f;
    int rr = -1;
    if (k < 128) rr = k;
    else { int q = k - 128; int chunk = q >> 6, w = q & 63; if (w < 62) rr = 128 + chunk*62 + w; }
    if (rr >= 0 && rr < dreal && j < 62) {
        const float* W0 = W;
        const float* W1 = W + (size_t)dreal*62;
        const float* W2 = W + (size_t)2*dreal*62;
        if (ch == 0)      val = W0[rr*62+j] - W2[rr*62+j];
        else if (ch == 1) val = W1[rr*62+j];
        else              val = 2.f * W2[rr*62+j];
    }
    u16 h, l; splitbf(val, h, l);
    int blk = k >> 6, kk = k & 63;
    size_t off = (size_t)blk*12288 + n*64 + kk;
    g_Wt_hi[layer][off] = h;
    g_Wt_lo[layer][off] = l;
}
__global__ void k_prepWh1t(const float* __restrict__ Wh1){
    int idx = blockIdx.x*256 + threadIdx.x;
    if (idx >= 248*512*8) return;
    int n = idx & 511;
    int q = idx >> 9;
    int blk = q >> 3, c8 = (q & 7) * 8;
    union { u16 u[8]; uint4 v; } H, L;
#pragma unroll
    for (int i = 0; i < 8; i++){
        int k = blk*64 + c8 + i;
        int node = k >> 8, cc = k & 255, ch = cc >> 6, w = cc & 63;
        float val = 0.f;
        if (w < 62) val = Wh1[((size_t)(node*248 + ch*62 + w))*LINW + n];
        splitbf(val, H.u[i], L.u[i]);
    }
    size_t off = ((size_t)blk*512 + n)*64 + c8;
    *(uint4*)(g_Wh1t_hi + off) = H.v;
    *(uint4*)(g_Wh1t_lo + off) = L.v;
}

// ---------------- mma.sync cheb GEMM + fused combine epilogue ----------------
// CTA: 128 M-rows (124 used = 2 graphs), N=192, k-chunks of 64.
// Warps 2(M)x4(N), warp tile 64x48. bf16x3 split accumulation in fp32.
#define CH_A_HI 0
#define CH_A_LO 16384
#define CH_B_HI 32768
#define CH_B_LO 57344
#define CH_SMEM 100352   // max(81920 tiles, 128*196*4 stage)

__global__ __launch_bounds__(256,1) void mm_cheb(int layer, int Kdim,
                                                 const float* __restrict__ bias, int cbase)
{
    extern __shared__ char smem[];
    const u32 sb = smem_u32(smem);
    const int t = threadIdx.x, wid = t >> 5, l = t & 31;
    const int wm = (wid & 1) * 64, wn = (wid >> 1) * 48;
    const int m0 = blockIdx.x * 124;
    const int nch = Kdim >> 6;
    const u16* Bh = g_Wt_hi[layer];
    const u16* Bl = g_Wt_lo[layer];

    float acc[4][6][4];
#pragma unroll
    for (int a = 0; a < 4; a++)
#pragma unroll
        for (int b = 0; b < 6; b++)
#pragma unroll
            for (int c = 0; c < 4; c++) acc[a][b][c] = 0.f;

    for (int c = 0; c < nch; c++){
        __syncthreads();
        int k0 = c << 6;
        // stage A (128 x 64 bf16, hi+lo), SW128 swizzle
        for (int i = t; i < 1024; i += 256){
            int r = i >> 3, cc = i & 7;
            int gr = m0 + r; if (gr > NN-1) gr = NN-1;
            size_t go = (size_t)gr*HROW + k0 + cc*8;
            u32 bo = swz((u32)(r*128 + cc*16));
            *(float4*)(smem + CH_A_HI + bo) = *(const float4*)(g_Hh + go);
            *(float4*)(smem + CH_A_LO + bo) = *(const float4*)(g_Hl + go);
        }
        // stage B (192 x 64 bf16, hi+lo)
        const u16* pbh = Bh + (size_t)c*12288;
        const u16* pbl = Bl + (size_t)c*12288;
        for (int i = t; i < 1536; i += 256){
            int r = i >> 3, cc = i & 7;
            u32 bo = swz((u32)(r*128 + cc*16));
            *(float4*)(smem + CH_B_HI + bo) = *(const float4*)(pbh + r*64 + cc*8);
            *(float4*)(smem + CH_B_LO + bo) = *(const float4*)(pbl + r*64 + cc*8);
        }
        __syncthreads();
#pragma unroll
        for (int ks = 0; ks < 4; ks++){
            u32 ah[4][4], al[4][4];
            int arow = wm + (l & 7) + ((l >> 3) & 1) * 8;
            int acol = ks*32 + ((l >> 4) & 1) * 16;
#pragma unroll
            for (int mi = 0; mi < 4; mi++){
                u32 bo = swz((u32)((arow + mi*16)*128 + acol));
                ldsm4(ah[mi][0],ah[mi][1],ah[mi][2],ah[mi][3], sb + CH_A_HI + bo);
                ldsm4(al[mi][0],al[mi][1],al[mi][2],al[mi][3], sb + CH_A_LO + bo);
            }
            u32 bh[3][4], bl[3][4];
            int brow = wn + (l & 7) + ((l >> 4) & 1) * 8;
            int bcol = ks*32 + ((l >> 3) & 1) * 16;
#pragma unroll
            for (int bi = 0; bi < 3; bi++){
                u32 bo = swz((u32)((brow + bi*16)*128 + bcol));
                ldsm4(bh[bi][0],bh[bi][1],bh[bi][2],bh[bi][3], sb + CH_B_HI + bo);
                ldsm4(bl[bi][0],bl[bi][1],bl[bi][2],bl[bi][3], sb + CH_B_LO + bo);
            }
#pragma unroll
            for (int mi = 0; mi < 4; mi++)
#pragma unroll
                for (int bi = 0; bi < 3; bi++){
                    mma_bf16(acc[mi][2*bi],   ah[mi], &bh[bi][0]);
                    mma_bf16(acc[mi][2*bi],   ah[mi], &bl[bi][0]);
                    mma_bf16(acc[mi][2*bi],   al[mi], &bh[bi][0]);
                    mma_bf16(acc[mi][2*bi+1], ah[mi], &bh[bi][2]);
                    mma_bf16(acc[mi][2*bi+1], ah[mi], &bl[bi][2]);
                    mma_bf16(acc[mi][2*bi+1], al[mi], &bh[bi][2]);
                }
        }
    }
    __syncthreads();

    // stage D -> smem [128][196]
    float* stg = (float*)smem;
#pragma unroll
    for (int mi = 0; mi < 4; mi++)
#pragma unroll
        for (int ni = 0; ni < 6; ni++){
            int row = wm + mi*16 + (l >> 2);
            int col = wn + ni*8 + (l & 3)*2;
            *(float2*)&stg[row*196 + col]     = make_float2(acc[mi][ni][0], acc[mi][ni][1]);
            *(float2*)&stg[(row+8)*196 + col] = make_float2(acc[mi][ni][2], acc[mi][ni][3]);
        }
    __syncthreads();

    // combine: out = P0 + L@P1 + L2@P2, bias, relu, split-write to H
    const int i0 = t >> 4, jj = (t & 15) * 4;
    for (int gi = 0; gi < 2; gi++){
        const float* Ps = stg + gi*62*196;
        size_t hrow0 = ((size_t)(blockIdx.x*2 + gi)) * 62;
        for (int ii = 0; ii < 4; ii++){
            int i = i0 + ii*16;
            if (i >= 62) continue;
            float4 a4 = *(const float4*)(Ps + i*196 + jj);
#pragma unroll 2
            for (int m = 0; m < 62; m++){
                float l1 = g_L [i*64 + m];
                float l2 = g_L2[i*64 + m];
                float4 p1 = *(const float4*)(Ps + m*196 +  64 + jj);
                float4 p2 = *(const float4*)(Ps + m*196 + 128 + jj);
                a4.x += l1*p1.x + l2*p2.x;
                a4.y += l1*p1.y + l2*p2.y;
                a4.z += l1*p1.z + l2*p2.z;
                a4.w += l1*p1.w + l2*p2.w;
            }
            float v[4] = {a4.x, a4.y, a4.z, a4.w};
            u16 hh[4], ll[4];
#pragma unroll
            for (int k = 0; k < 4; k++){
                int j = jj + k;
                float val = (j < 62) ? fmaxf(v[k] + bias[j], 0.f) : 0.f;
                splitbf(val, hh[k], ll[k]);
            }
            size_t off = (hrow0 + i)*HROW + cbase + jj;
            *(u32*)(g_Hh + off)     = (u32)hh[0] | ((u32)hh[1] << 16);
            *(u32*)(g_Hh + off + 2) = (u32)hh[2] | ((u32)hh[3] << 16);
            *(u32*)(g_Hl + off)     = (u32)ll[0] | ((u32)ll[1] << 16);
            *(u32*)(g_Hl + off + 2) = (u32)ll[2] | ((u32)ll[3] << 16);
        }
    }
}

// ---------------- mma.sync feats GEMM (split-K=4, tile 128x128) ----------------
#define FT_A_HI 0
#define FT_A_LO 16384
#define FT_B_HI 32768
#define FT_B_LO 49152
#define FT_SMEM 65536

__global__ __launch_bounds__(256,1) void mm_feats()
{
    extern __shared__ char smem[];
    const u32 sb = smem_u32(smem);
    const int t = threadIdx.x, wid = t >> 5, l = t & 31;
    const int wm = (wid & 1) * 64, wn = (wid >> 1) * 32;
    const int n0 = blockIdx.x * 128;
    const int m0 = blockIdx.y * 128;
    const int part = blockIdx.z;
    const int cbeg = part * 62;

    float acc[4][4][4];
#pragma unroll
    for (int a = 0; a < 4; a++)
#pragma unroll
        for (int b = 0; b < 4; b++)
#pragma unroll
            for (int c = 0; c < 4; c++) acc[a][b][c] = 0.f;

    for (int cl = 0; cl < 62; cl++){
        __syncthreads();
        int c = cbeg + cl;
        int node = c >> 2, col0 = 128 + ((c & 3) << 6);
        // A: 128 graph-rows x 64 (in-place gather from H), hi+lo
        for (int i = t; i < 1024; i += 256){
            int r = i >> 3, cc = i & 7;
            size_t go = ((size_t)(m0 + r)*62 + node)*HROW + col0 + cc*8;
            u32 bo = swz((u32)(r*128 + cc*16));
            *(float4*)(smem + FT_A_HI + bo) = *(const float4*)(g_Hh + go);
            *(float4*)(smem + FT_A_LO + bo) = *(const float4*)(g_Hl + go);
        }
        // B: 128 n-rows x 64, hi+lo
        const u16* pbh = g_Wh1t_hi + ((size_t)c*512 + n0)*64;
        const u16* pbl = g_Wh1t_lo + ((size_t)c*512 + n0)*64;
        for (int i = t; i < 1024; i += 256){
            int r = i >> 3, cc = i & 7;
            u32 bo = swz((u32)(r*128 + cc*16));
            *(float4*)(smem + FT_B_HI + bo) = *(const float4*)(pbh + r*64 + cc*8);
            *(float4*)(smem + FT_B_LO + bo) = *(const float4*)(pbl + r*64 + cc*8);
        }
        __syncthreads();
#pragma unroll
        for (int ks = 0; ks < 4; ks++){
            u32 ah[4][4], al[4][4];
            int arow = wm + (l & 7) + ((l >> 3) & 1) * 8;
            int acol = ks*32 + ((l >> 4) & 1) * 16;
#pragma unroll
            for (int mi = 0; mi < 4; mi++){
                u32 bo = swz((u32)((arow + mi*16)*128 + acol));
                ldsm4(ah[mi][0],ah[mi][1],ah[mi][2],ah[mi][3], sb + FT_A_HI + bo);
                ldsm4(al[mi][0],al[mi][1],al[mi][2],al[mi][3], sb + FT_A_LO + bo);
            }
            u32 bh[2][4], bl[2][4];
            int brow = wn + (l & 7) + ((l >> 4) & 1) * 8;
            int bcol = ks*32 + ((l >> 3) & 1) * 16;
#pragma unroll
            for (int bi = 0; bi < 2; bi++){
                u32 bo = swz((u32)((brow + bi*16)*128 + bcol));
                ldsm4(bh[bi][0],bh[bi][1],bh[bi][2],bh[bi][3], sb + FT_B_HI + bo);
                ldsm4(bl[bi][0],bl[bi][1],bl[bi][2],bl[bi][3], sb + FT_B_LO + bo);
            }
#pragma unroll
            for (int mi = 0; mi < 4; mi++)
#pragma unroll
                for (int bi = 0; bi < 2; bi++){
                    mma_bf16(acc[mi][2*bi],   ah[mi], &bh[bi][0]);
                    mma_bf16(acc[mi][2*bi],   ah[mi], &bl[bi][0]);
                    mma_bf16(acc[mi][2*bi],   al[mi], &bh[bi][0]);
                    mma_bf16(acc[mi][2*bi+1], ah[mi], &bh[bi][2]);
                    mma_bf16(acc[mi][2*bi+1], ah[mi], &bl[bi][2]);
                    mma_bf16(acc[mi][2*bi+1], al[mi], &bh[bi][2]);
                }
        }
    }

    // direct writeout of partials
    float* outp = g_G1p + (size_t)part*BATCHG*LINW;
#pragma unroll
    for (int mi = 0; mi < 4; mi++)
#pragma unroll
        for (int ni = 0; ni < 4; ni++){
            int row = m0 + wm + mi*16 + (l >> 2);
            int col = n0 + wn + ni*8 + (l & 3)*2;
            *(float2*)&outp[(size_t)row*LINW + col]     = make_float2(acc[mi][ni][0], acc[mi][ni][1]);
            *(float2*)&outp[(size_t)(row+8)*LINW + col] = make_float2(acc[mi][ni][2], acc[mi][ni][3]);
        }
}

__global__ void k_reduceK(){
    int t = blockIdx.x*256 + threadIdx.x;
    if (t >= BATCHG*LINW) return;
    float s = 0.f;
#pragma unroll
    for (int p = 0; p < KSPLIT; p++) s += g_G1p[(size_t)p*BATCHG*LINW + t];
    g_G1[t] = s;
}

// ---------------- SIMT fp32 GEMM for Wh2 (small) ----------------
__global__ void gemm_s(const float* __restrict__ A, const float* __restrict__ B,
                       float* __restrict__ C, int N, int K, int lda, int ldb, int ldc)
{
    __shared__ float As[16][68];
    __shared__ float Bs[16][64];
    int t = threadIdx.x;
    int m0 = blockIdx.y * 64, n0 = blockIdx.x * 64;
    int ty = t >> 4, tx = t & 15;
    int am = t >> 2, ak = (t & 3) * 4;
    int bk = t >> 4, bn = (t & 15) * 4;
    float acc[4][4];
#pragma unroll
    for (int i = 0; i < 4; i++)
#pragma unroll
        for (int j = 0; j < 4; j++) acc[i][j] = 0.f;
    for (int k0 = 0; k0 < K; k0 += 16) {
        float4 av = *reinterpret_cast<const float4*>(A + (size_t)(m0+am)*lda + k0 + ak);
        As[ak+0][am] = av.x; As[ak+1][am] = av.y; As[ak+2][am] = av.z; As[ak+3][am] = av.w;
        float4 bv = *reinterpret_cast<const float4*>(B + (size_t)(k0+bk)*ldb + n0 + bn);
        *reinterpret_cast<float4*>(&Bs[bk][bn]) = bv;
        __syncthreads();
#pragma unroll
        for (int k = 0; k < 16; k++) {
            float4 a4 = *reinterpret_cast<const float4*>(&As[k][ty*4]);
            float4 b4 = *reinterpret_cast<const float4*>(&Bs[k][tx*4]);
            float a[4] = {a4.x, a4.y, a4.z, a4.w};
            float b[4] = {b4.x, b4.y, b4.z, b4.w};
#pragma unroll
            for (int i = 0; i < 4; i++)
#pragma unroll
                for (int j = 0; j < 4; j++) acc[i][j] += a[i]*b[j];
        }
        __syncthreads();
    }
#pragma unroll
    for (int i = 0; i < 4; i++) {
        float4 v = make_float4(acc[i][0], acc[i][1], acc[i][2], acc[i][3]);
        *reinterpret_cast<float4*>(C + (size_t)(m0 + ty*4 + i)*ldc + n0 + tx*4) = v;
    }
}

// ---------------- batchnorm / final ----------------
__global__ void k_bnstats(const float* __restrict__ X, int ld){
    int c = blockIdx.x;
    int t = threadIdx.x;
    float s = 0.f, sq = 0.f;
    for (int r = t; r < BATCHG; r += 256) {
        float v = X[(size_t)r*ld + c];
        s += v; sq += v*v;
    }
    __shared__ float sh[256], sh2[256];
    sh[t] = s; sh2[t] = sq; __syncthreads();
    for (int o = 128; o > 0; o >>= 1) {
        if (t < o) { sh[t] += sh[t+o]; sh2[t] += sh2[t+o]; }
        __syncthreads();
    }
    if (t == 0) {
        float m = sh[0] * (1.f/BATCHG);
        float v = sh2[0] * (1.f/BATCHG) - m*m;
        g_mean[c] = m;
        g_rstd[c] = rsqrtf(v + 1e-5f);
    }
}
__global__ void k_bnrelu(float* __restrict__ X, int nc,
                         const float* __restrict__ gamma, const float* __restrict__ beta){
    int idx = blockIdx.x*256 + threadIdx.x;
    if (idx >= BATCHG*nc) return;
    int c = idx % nc;
    float v = X[idx];
    v = (v - g_mean[c]) * g_rstd[c] * gamma[c] + beta[c];
    X[idx] = fmaxf(v, 0.f);
}
__global__ void k_final(const float* __restrict__ Wh3, const float* __restrict__ bh3,
                        float* __restrict__ out){
    int r = blockIdx.x*256 + threadIdx.x;
    if (r >= BATCHG) return;
    const float* h = g_G2 + (size_t)r * LIN2;
    float a0 = bh3[0], a1 = bh3[1], a2 = bh3[2];
    for (int k = 0; k < LIN2; k++) {
        float v = h[k];
        a0 += v * Wh3[k*3+0];
        a1 += v * Wh3[k*3+1];
        a2 += v * Wh3[k*3+2];
    }
    float mx = fmaxf(a0, fmaxf(a1, a2));
    float e0 = expf(a0-mx), e1 = expf(a1-mx), e2 = expf(a2-mx);
    float inv = 1.f / (e0+e1+e2);
    out[r*3+0] = e0*inv; out[r*3+1] = e1*inv; out[r*3+2] = e2*inv;
}

// ---------------- launch ----------------
extern "C" void kernel_launch(void* const* d_in, const int* in_sizes, int n_in,
                              void* d_out, int out_size) {
    const float* x   = (const float*)d_in[0];
    const int*   ei  = (const int*)  d_in[1];
    const float* W[4]  = {(const float*)d_in[2], (const float*)d_in[4],
                          (const float*)d_in[6], (const float*)d_in[8]};
    const float* bb[4] = {(const float*)d_in[3], (const float*)d_in[5],
                          (const float*)d_in[7], (const float*)d_in[9]};
    const float* Wh1 = (const float*)d_in[10];
    const float* g1  = (const float*)d_in[12];
    const float* be1 = (const float*)d_in[13];
    const float* Wh2 = (const float*)d_in[14];
    const float* g2  = (const float*)d_in[16];
    const float* be2 = (const float*)d_in[17];
    const float* Wh3 = (const float*)d_in[18];
    const float* bh3 = (const float*)d_in[19];
    float* out = (float*)d_out;

    int E = in_sizes[1] / 2;
    const int* row = ei;
    const int* col = ei + E;

    float *hG1, *hG2;
    cudaGetSymbolAddress((void**)&hG1, g_G1);
    cudaGetSymbolAddress((void**)&hG2, g_G2);

    cudaFuncSetAttribute(mm_cheb,  cudaFuncAttributeMaxDynamicSharedMemorySize, CH_SMEM);
    cudaFuncSetAttribute(mm_feats, cudaFuncAttributeMaxDynamicSharedMemorySize, FT_SMEM);

    const int DPAD[4]  = {128, 192, 256, 320};
    const int DREAL[4] = {128, 190, 252, 314};

    // init H + Laplacian
    {
        size_t total = (size_t)NN*16;
        k_init_H<<<(unsigned)((total + 255)/256), 256>>>(x);
    }
    k_deg<<<1, 512>>>(row);
    k_build_L<<<1, 512>>>(row, col);
    k_L2<<<16, 256>>>();

    // weight prep
    for (int i = 0; i < 4; i++) {
        int n = DPAD[i]*192;
        k_prepWt<<<(n+255)/256, 256>>>(W[i], DREAL[i], DPAD[i], i);
    }
    k_prepWh1t<<<(248*512*8 + 255)/256, 256>>>(Wh1);

    // 4 cheb layers (GEMM + fused combine)
    for (int i = 0; i < 4; i++)
        mm_cheb<<<1024, 256, CH_SMEM>>>(i, DPAD[i], bb[i], 128 + 64*i);

    // MLP head
    mm_feats<<<dim3(4, 16, KSPLIT), 256, FT_SMEM>>>();
    k_reduceK<<<(BATCHG*LINW + 255)/256, 256>>>();
    k_bnstats<<<LINW, 256>>>(hG1, LINW);
    k_bnrelu<<<(BATCHG*LINW + 255)/256, 256>>>(hG1, LINW, g1, be1);

    gemm_s<<<dim3(LIN2/64, BATCHG/64), 256>>>(hG1, Wh2, hG2, LIN2, LINW, LINW, LIN2, LIN2);
    k_bnstats<<<LIN2, 256>>>(hG2, LIN2);
    k_bnrelu<<<(BATCHG*LIN2 + 255)/256, 256>>>(hG2, LIN2, g2, be2);

    k_final<<<(BATCHG + 255)/256, 256>>>(Wh3, bh3, out);
}

// round 5
// speedup vs baseline: 3.0686x; 2.3758x over previous
#include <cuda_runtime.h>
#include <cuda_bf16.h>

typedef unsigned short u16;
typedef unsigned int   u32;
typedef unsigned long long u64;

#define NODES 62
#define BATCHG 2048
#define NN (NODES*BATCHG)          // 126976
#define HROW 384                   // x:0-128 | x1:128-192 | x2:192-256 | x3:256-320 | x4:320-384
#define LINW 512
#define LIN2 256
#define KSPLIT 4
#define EPB 496

// ---------------- static device scratch ----------------
__device__ u16 g_Hh[(size_t)NN*HROW];          // H hi bf16 (97MB)
__device__ u16 g_Hl[(size_t)NN*HROW];          // H lo bf16
__device__ u16 g_Wt_hi[4][5*192*64];           // cheb weights, transposed [blk][n][64]
__device__ u16 g_Wt_lo[4][5*192*64];
__device__ u16 g_Wh1t_hi[(size_t)248*512*64];  // Wh1 transposed blocks
__device__ u16 g_Wh1t_lo[(size_t)248*512*64];
__device__ u16 g_LA[4*4096];                   // [hl][kb][64 m][64 k] bf16 split of [L|L2]
__device__ float g_G1p[(size_t)KSPLIT*BATCHG*LINW];
__device__ float g_G1[BATCHG*LINW];
__device__ float g_G2[BATCHG*LIN2];
__device__ float g_L[62*64];
__device__ float g_L2[62*64];
__device__ float g_deg[64];
__device__ float g_mean[LINW];
__device__ float g_rstd[LINW];

// ---------------- helpers ----------------
__device__ __forceinline__ u32 smem_u32(const void* p){
    u32 a;
    asm("{ .reg .u64 t; cvta.to.shared.u64 t, %1; cvt.u32.u64 %0, t; }" : "=r"(a) : "l"(p));
    return a;
}
__device__ __forceinline__ void ldsm4(u32& r0,u32& r1,u32& r2,u32& r3,u32 addr){
    asm volatile("ldmatrix.sync.aligned.m8n8.x4.shared.b16 {%0,%1,%2,%3}, [%4];"
        : "=r"(r0),"=r"(r1),"=r"(r2),"=r"(r3) : "r"(addr));
}
__device__ __forceinline__ void mma_bf16(float* d, const u32* a, const u32* b){
    asm volatile("mma.sync.aligned.m16n8k16.row.col.f32.bf16.bf16.f32 "
        "{%0,%1,%2,%3}, {%4,%5,%6,%7}, {%8,%9}, {%0,%1,%2,%3};"
        : "+f"(d[0]),"+f"(d[1]),"+f"(d[2]),"+f"(d[3])
        : "r"(a[0]),"r"(a[1]),"r"(a[2]),"r"(a[3]), "r"(b[0]),"r"(b[1]));
}
__device__ __forceinline__ u32 swz(u32 bo){ return bo ^ ((bo >> 3) & 0x70); }
__device__ __forceinline__ void splitbf(float v, u16& h, u16& l){
    __nv_bfloat16 bh = __float2bfloat16(v);
    __nv_bfloat16 bl = __float2bfloat16(v - __bfloat162float(bh));
    h = *reinterpret_cast<u16*>(&bh);
    l = *reinterpret_cast<u16*>(&bl);
}
__device__ __forceinline__ void cpa16(u32 dst, const void* src){
    asm volatile("cp.async.cg.shared.global [%0], [%1], 16;" :: "r"(dst), "l"(src));
}
__device__ __forceinline__ void cpa_commit(){ asm volatile("cp.async.commit_group;"); }
template<int N> __device__ __forceinline__ void cpa_wait(){
    asm volatile("cp.async.wait_group %0;" :: "n"(N));
}

// ---------------- init: H[:,0:128] = split(x) ----------------
__global__ void k_init_H(const float* __restrict__ x){
    size_t idx = (size_t)blockIdx.x*256 + threadIdx.x;
    if (idx >= (size_t)NN*16) return;
    size_t r = idx >> 4;
    int c8 = ((int)idx & 15) * 8;
    float4 a = *(const float4*)(x + r*128 + c8);
    float4 b = *(const float4*)(x + r*128 + c8 + 4);
    float v[8] = {a.x,a.y,a.z,a.w,b.x,b.y,b.z,b.w};
    union { u16 u[8]; uint4 q; } H, L;
#pragma unroll
    for (int i = 0; i < 8; i++) splitbf(v[i], H.u[i], L.u[i]);
    *(uint4*)(g_Hh + r*HROW + c8) = H.q;
    *(uint4*)(g_Hl + r*HROW + c8) = L.q;
}

// ---------------- graph Laplacian (graph 0 == all graphs) ----------------
__global__ void k_deg(const int* __restrict__ row){
    int t = threadIdx.x;
    if (t < 64) g_deg[t] = 0.f;
    __syncthreads();
    if (t < EPB) atomicAdd(&g_deg[row[t]], 1.0f);
}
__global__ void k_build_L(const int* __restrict__ row, const int* __restrict__ col){
    int t = threadIdx.x;
    for (int i = t; i < 62*64; i += 512) { g_L[i] = 0.f; g_L2[i] = 0.f; }
    __syncthreads();
    if (t < EPB) {
        int r = row[t], c = col[t];
        float w = -rsqrtf(g_deg[r]) * rsqrtf(g_deg[c]);
        atomicAdd(&g_L[r*64 + c], w);
    }
}
__global__ void k_L2(){
    int t = blockIdx.x*256 + threadIdx.x;
    if (t >= 62*64) return;
    int i = t / 64, j = t % 64;
    float s = 0.f;
    if (j < 62)
        for (int m = 0; m < 62; m++) s += g_L[i*64+m] * g_L[m*64+j];
    g_L2[t] = s;
}
// [L|L2] bf16 split, [hl][kb][m 64][k 64]
__global__ void k_prepLA(){
    int t = blockIdx.x*256 + threadIdx.x;
    if (t >= 8192) return;
    int kb = t >> 12, rem = t & 4095;
    int m = rem >> 6, k = rem & 63;
    float val = 0.f;
    if (m < 62 && k < 62) val = kb ? g_L2[m*64+k] : g_L[m*64+k];
    u16 h, l; splitbf(val, h, l);
    g_LA[kb*4096 + rem] = h;
    g_LA[8192 + kb*4096 + rem] = l;
}

// ---------------- weight prep (transposed + bf16 split) ----------------
__global__ void k_prepWt(const float* __restrict__ W, int dreal, int dpad, int layer){
    int t = blockIdx.x*256 + threadIdx.x;
    if (t >= dpad*192) return;
    int n = t % 192, k = t / 192;
    int ch = n >> 6, j = n & 63;
    float val = 0.f;
    int rr = -1;
    if (k < 128) rr = k;
    else { int q = k - 128; int chunk = q >> 6, w = q & 63; if (w < 62) rr = 128 + chunk*62 + w; }
    if (rr >= 0 && rr < dreal && j < 62) {
        const float* W0 = W;
        const float* W1 = W + (size_t)dreal*62;
        const float* W2 = W + (size_t)2*dreal*62;
        if (ch == 0)      val = W0[rr*62+j] - W2[rr*62+j];
        else if (ch == 1) val = W1[rr*62+j];
        else              val = 2.f * W2[rr*62+j];
    }
    u16 h, l; splitbf(val, h, l);
    int blk = k >> 6, kk = k & 63;
    size_t off = (size_t)blk*12288 + n*64 + kk;
    g_Wt_hi[layer][off] = h;
    g_Wt_lo[layer][off] = l;
}
__global__ void k_prepWh1t(const float* __restrict__ Wh1){
    int idx = blockIdx.x*256 + threadIdx.x;
    if (idx >= 248*512*8) return;
    int n = idx & 511;
    int q = idx >> 9;
    int blk = q >> 3, c8 = (q & 7) * 8;
    union { u16 u[8]; uint4 v; } H, L;
#pragma unroll
    for (int i = 0; i < 8; i++){
        int k = blk*64 + c8 + i;
        int node = k >> 8, cc = k & 255, ch = cc >> 6, w = cc & 63;
        float val = 0.f;
        if (w < 62) val = Wh1[((size_t)(node*248 + ch*62 + w))*LINW + n];
        splitbf(val, H.u[i], L.u[i]);
    }
    size_t off = ((size_t)blk*512 + n)*64 + c8;
    *(uint4*)(g_Wh1t_hi + off) = H.v;
    *(uint4*)(g_Wh1t_lo + off) = L.v;
}

// ---------------- mma.sync cheb GEMM + MMA combine epilogue ----------------
// CTA: 128 M-rows (124 used = 2 graphs), N=192, k-chunks of 64, cp.async double buffer.
#define CH_A_HI 0
#define CH_A_LO 16384
#define CH_B_HI 32768
#define CH_B_LO 57344
#define CH_BUF  81920
#define CH_ST   0        // stage P0 f32 [128][64] (32KB)
#define CH_BT   32768    // Bt [g2][hl2][kb2][feat 64][node 64] bf16 (64KB)
#define CH_AL   98304    // A_L [hl2][kb2][64][64] bf16 (32KB)
#define CH_SMEM 163840

__global__ __launch_bounds__(256,1) void mm_cheb(int layer, int Kdim,
                                                 const float* __restrict__ bias, int cbase)
{
    extern __shared__ char smem[];
    const u32 sb = smem_u32(smem);
    const int t = threadIdx.x, wid = t >> 5, l = t & 31;
    const int wm = (wid & 1) * 64, wn = (wid >> 1) * 48;
    const int m0 = blockIdx.x * 124;
    const int nch = Kdim >> 6;
    const u16* Bh = g_Wt_hi[layer];
    const u16* Bl = g_Wt_lo[layer];

    float acc[4][6][4];
#pragma unroll
    for (int a = 0; a < 4; a++)
#pragma unroll
        for (int b = 0; b < 6; b++)
#pragma unroll
            for (int c = 0; c < 4; c++) acc[a][b][c] = 0.f;

    // ---- stage helper (cp.async) ----
    auto stage = [&](int c){
        u32 bufb = sb + (c & 1) * CH_BUF;
        int k0 = c << 6;
        for (int i = t; i < 1024; i += 256){
            int r = i >> 3, cc = i & 7;
            int gr = m0 + r; if (gr > NN-1) gr = NN-1;
            size_t go = (size_t)gr*HROW + k0 + cc*8;
            u32 bo = swz((u32)(r*128 + cc*16));
            cpa16(bufb + CH_A_HI + bo, g_Hh + go);
            cpa16(bufb + CH_A_LO + bo, g_Hl + go);
        }
        const u16* pbh = Bh + (size_t)c*12288;
        const u16* pbl = Bl + (size_t)c*12288;
        for (int i = t; i < 1536; i += 256){
            int r = i >> 3, cc = i & 7;
            u32 bo = swz((u32)(r*128 + cc*16));
            cpa16(bufb + CH_B_HI + bo, pbh + r*64 + cc*8);
            cpa16(bufb + CH_B_LO + bo, pbl + r*64 + cc*8);
        }
        cpa_commit();
    };

    stage(0);
    for (int c = 0; c < nch; c++){
        if (c+1 < nch) { stage(c+1); cpa_wait<1>(); }
        else cpa_wait<0>();
        __syncthreads();
        u32 bufb = sb + (c & 1) * CH_BUF;
#pragma unroll
        for (int ks = 0; ks < 4; ks++){
            u32 ah[4][4], al[4][4];
            int arow = wm + (l & 7) + ((l >> 3) & 1) * 8;
            int acol = ks*32 + ((l >> 4) & 1) * 16;
#pragma unroll
            for (int mi = 0; mi < 4; mi++){
                u32 bo = swz((u32)((arow + mi*16)*128 + acol));
                ldsm4(ah[mi][0],ah[mi][1],ah[mi][2],ah[mi][3], bufb + CH_A_HI + bo);
                ldsm4(al[mi][0],al[mi][1],al[mi][2],al[mi][3], bufb + CH_A_LO + bo);
            }
            u32 bh4[3][4], bl4[3][4];
            int brow = wn + (l & 7) + ((l >> 4) & 1) * 8;
            int bcol = ks*32 + ((l >> 3) & 1) * 16;
#pragma unroll
            for (int bi = 0; bi < 3; bi++){
                u32 bo = swz((u32)((brow + bi*16)*128 + bcol));
                ldsm4(bh4[bi][0],bh4[bi][1],bh4[bi][2],bh4[bi][3], bufb + CH_B_HI + bo);
                ldsm4(bl4[bi][0],bl4[bi][1],bl4[bi][2],bl4[bi][3], bufb + CH_B_LO + bo);
            }
#pragma unroll
            for (int mi = 0; mi < 4; mi++)
#pragma unroll
                for (int bi = 0; bi < 3; bi++){
                    mma_bf16(acc[mi][2*bi],   ah[mi], &bh4[bi][0]);
                    mma_bf16(acc[mi][2*bi],   ah[mi], &bl4[bi][0]);
                    mma_bf16(acc[mi][2*bi],   al[mi], &bh4[bi][0]);
                    mma_bf16(acc[mi][2*bi+1], ah[mi], &bh4[bi][2]);
                    mma_bf16(acc[mi][2*bi+1], ah[mi], &bl4[bi][2]);
                    mma_bf16(acc[mi][2*bi+1], al[mi], &bh4[bi][2]);
                }
        }
        __syncthreads();
    }

    // ---- combine epilogue: out = P0 + [L|L2]@[P1;P2], via MMA ----
    // zero Bt + load A_L
    for (int i = t; i < 4096; i += 256)
        *(float4*)(smem + CH_BT + i*16) = make_float4(0.f,0.f,0.f,0.f);
    for (int i = t; i < 2048; i += 256){
        int blk = i >> 9, rem = i & 511;
        int r = rem >> 3, cc = rem & 7;
        u32 bo = swz((u32)(r*128 + cc*16));
        *(float4*)(smem + CH_AL + blk*8192 + bo) = *(const float4*)(g_LA + blk*4096 + r*64 + cc*8);
    }
    __syncthreads();
    // transpose-store: cols<64 -> stage f32, cols>=64 -> Bt bf16 split [feat][node]
    {
        float* stg = (float*)(smem + CH_ST);
#pragma unroll
        for (int mi = 0; mi < 4; mi++)
#pragma unroll
            for (int ni = 0; ni < 6; ni++)
#pragma unroll
                for (int rp = 0; rp < 4; rp += 2){
                    int row = wm + mi*16 + (l>>2) + (rp ? 8 : 0);
                    int col = wn + ni*8 + (l&3)*2;
                    float v0 = acc[mi][ni][rp], v1 = acc[mi][ni][rp+1];
                    if (col < 64){
                        *(float2*)&stg[row*64 + col] = make_float2(v0, v1);
                    } else if (row < 124){
                        int g = (row >= 62) ? 1 : 0;
                        int node = row - g*62;
                        int kbB = (col >= 128) ? 1 : 0;
                        int feat = col - (kbB ? 128 : 64);
                        u16 h0,l0,h1,l1; splitbf(v0,h0,l0); splitbf(v1,h1,l1);
                        u32 b0 = CH_BT + g*32768 + kbB*8192 + swz((u32)(feat*128 + node*2));
                        u32 b1 = CH_BT + g*32768 + kbB*8192 + swz((u32)((feat+1)*128 + node*2));
                        *(u16*)(smem + b0) = h0;  *(u16*)(smem + b1) = h1;
                        *(u16*)(smem + b0 + 16384) = l0; *(u16*)(smem + b1 + 16384) = l1;
                    }
                }
    }
    __syncthreads();
    // combine MMA: per warp: graph g = wid>>2, m-tile mt = wid&3; M=16, N=64, K=128
    {
        int g = wid >> 2, mt = wid & 3;
        float a2[8][4];
#pragma unroll
        for (int j = 0; j < 8; j++)
#pragma unroll
            for (int r = 0; r < 4; r++) a2[j][r] = 0.f;
#pragma unroll
        for (int kb = 0; kb < 2; kb++)
#pragma unroll
            for (int k16 = 0; k16 < 4; k16++){
                u32 Ah[4], Al4[4];
                u32 boA = swz((u32)((mt*16 + (l&7) + ((l>>3)&1)*8)*128 + k16*32 + ((l>>4)&1)*16));
                ldsm4(Ah[0],Ah[1],Ah[2],Ah[3],     sb + CH_AL + kb*8192 + boA);
                ldsm4(Al4[0],Al4[1],Al4[2],Al4[3], sb + CH_AL + 16384 + kb*8192 + boA);
#pragma unroll
                for (int np = 0; np < 4; np++){
                    u32 Bh4[4], Bl4[4];
                    u32 boB = swz((u32)((np*16 + (l&7) + ((l>>4)&1)*8)*128 + k16*32 + ((l>>3)&1)*16));
                    u32 bbase = sb + CH_BT + g*32768 + kb*8192 + boB;
                    ldsm4(Bh4[0],Bh4[1],Bh4[2],Bh4[3], bbase);
                    ldsm4(Bl4[0],Bl4[1],Bl4[2],Bl4[3], bbase + 16384);
                    mma_bf16(a2[2*np],   Ah,  &Bh4[0]);
                    mma_bf16(a2[2*np],   Ah,  &Bl4[0]);
                    mma_bf16(a2[2*np],   Al4, &Bh4[0]);
                    mma_bf16(a2[2*np+1], Ah,  &Bh4[2]);
                    mma_bf16(a2[2*np+1], Ah,  &Bl4[2]);
                    mma_bf16(a2[2*np+1], Al4, &Bh4[2]);
                }
            }
        // write: val = a2 + P0 + bias, relu, bf16 split
        float* stg = (float*)(smem + CH_ST);
        size_t hrow0 = ((size_t)(blockIdx.x*2 + g)) * 62;
#pragma unroll
        for (int j = 0; j < 8; j++)
#pragma unroll
            for (int rp = 0; rp < 4; rp += 2){
                int node = mt*16 + (l>>2) + (rp ? 8 : 0);
                if (node >= 62) continue;
                int col = j*8 + (l&3)*2;
                float v0 = a2[j][rp]   + stg[(g*62+node)*64 + col];
                float v1 = a2[j][rp+1] + stg[(g*62+node)*64 + col+1];
                v0 = (col   < 62) ? fmaxf(v0 + bias[col],   0.f) : 0.f;
                v1 = (col+1 < 62) ? fmaxf(v1 + bias[col+1], 0.f) : 0.f;
                u16 h0,l0,h1,l1; splitbf(v0,h0,l0); splitbf(v1,h1,l1);
                size_t off = (hrow0 + node)*HROW + cbase + col;
                *(u32*)(g_Hh + off) = (u32)h0 | ((u32)h1 << 16);
                *(u32*)(g_Hl + off) = (u32)l0 | ((u32)l1 << 16);
            }
    }
}

// ---------------- mma.sync feats GEMM (split-K=4, tile 128x128, cp.async) ------
#define FT_A_HI 0
#define FT_A_LO 16384
#define FT_B_HI 32768
#define FT_B_LO 49152
#define FT_BUF  65536
#define FT_SMEM 131072

__global__ __launch_bounds__(256,1) void mm_feats()
{
    extern __shared__ char smem[];
    const u32 sb = smem_u32(smem);
    const int t = threadIdx.x, wid = t >> 5, l = t & 31;
    const int wm = (wid & 1) * 64, wn = (wid >> 1) * 32;
    const int n0 = blockIdx.x * 128;
    const int m0 = blockIdx.y * 128;
    const int part = blockIdx.z;
    const int cbeg = part * 62;

    float acc[4][4][4];
#pragma unroll
    for (int a = 0; a < 4; a++)
#pragma unroll
        for (int b = 0; b < 4; b++)
#pragma unroll
            for (int c = 0; c < 4; c++) acc[a][b][c] = 0.f;

    auto stage = [&](int cl){
        u32 bufb = sb + (cl & 1) * FT_BUF;
        int c = cbeg + cl;
        int node = c >> 2, col0 = 128 + ((c & 3) << 6);
        for (int i = t; i < 1024; i += 256){
            int r = i >> 3, cc = i & 7;
            size_t go = ((size_t)(m0 + r)*62 + node)*HROW + col0 + cc*8;
            u32 bo = swz((u32)(r*128 + cc*16));
            cpa16(bufb + FT_A_HI + bo, g_Hh + go);
            cpa16(bufb + FT_A_LO + bo, g_Hl + go);
        }
        const u16* pbh = g_Wh1t_hi + ((size_t)c*512 + n0)*64;
        const u16* pbl = g_Wh1t_lo + ((size_t)c*512 + n0)*64;
        for (int i = t; i < 1024; i += 256){
            int r = i >> 3, cc = i & 7;
            u32 bo = swz((u32)(r*128 + cc*16));
            cpa16(bufb + FT_B_HI + bo, pbh + r*64 + cc*8);
            cpa16(bufb + FT_B_LO + bo, pbl + r*64 + cc*8);
        }
        cpa_commit();
    };

    stage(0);
    for (int cl = 0; cl < 62; cl++){
        if (cl+1 < 62) { stage(cl+1); cpa_wait<1>(); }
        else cpa_wait<0>();
        __syncthreads();
        u32 bufb = sb + (cl & 1) * FT_BUF;
#pragma unroll
        for (int ks = 0; ks < 4; ks++){
            u32 ah[4][4], al[4][4];
            int arow = wm + (l & 7) + ((l >> 3) & 1) * 8;
            int acol = ks*32 + ((l >> 4) & 1) * 16;
#pragma unroll
            for (int mi = 0; mi < 4; mi++){
                u32 bo = swz((u32)((arow + mi*16)*128 + acol));
                ldsm4(ah[mi][0],ah[mi][1],ah[mi][2],ah[mi][3], bufb + FT_A_HI + bo);
                ldsm4(al[mi][0],al[mi][1],al[mi][2],al[mi][3], bufb + FT_A_LO + bo);
            }
            u32 bh4[2][4], bl4[2][4];
            int brow = wn + (l & 7) + ((l >> 4) & 1) * 8;
            int bcol = ks*32 + ((l >> 3) & 1) * 16;
#pragma unroll
            for (int bi = 0; bi < 2; bi++){
                u32 bo = swz((u32)((brow + bi*16)*128 + bcol));
                ldsm4(bh4[bi][0],bh4[bi][1],bh4[bi][2],bh4[bi][3], bufb + FT_B_HI + bo);
                ldsm4(bl4[bi][0],bl4[bi][1],bl4[bi][2],bl4[bi][3], bufb + FT_B_LO + bo);
            }
#pragma unroll
            for (int mi = 0; mi < 4; mi++)
#pragma unroll
                for (int bi = 0; bi < 2; bi++){
                    mma_bf16(acc[mi][2*bi],   ah[mi], &bh4[bi][0]);
                    mma_bf16(acc[mi][2*bi],   ah[mi], &bl4[bi][0]);
                    mma_bf16(acc[mi][2*bi],   al[mi], &bh4[bi][0]);
                    mma_bf16(acc[mi][2*bi+1], ah[mi], &bh4[bi][2]);
                    mma_bf16(acc[mi][2*bi+1], ah[mi], &bl4[bi][2]);
                    mma_bf16(acc[mi][2*bi+1], al[mi], &bh4[bi][2]);
                }
        }
        __syncthreads();
    }

    float* outp = g_G1p + (size_t)part*BATCHG*LINW;
#pragma unroll
    for (int mi = 0; mi < 4; mi++)
#pragma unroll
        for (int ni = 0; ni < 4; ni++){
            int row = m0 + wm + mi*16 + (l >> 2);
            int col = n0 + wn + ni*8 + (l & 3)*2;
            *(float2*)&outp[(size_t)row*LINW + col]     = make_float2(acc[mi][ni][0], acc[mi][ni][1]);
            *(float2*)&outp[(size_t)(row+8)*LINW + col] = make_float2(acc[mi][ni][2], acc[mi][ni][3]);
        }
}

__global__ void k_reduceK(){
    int t = blockIdx.x*256 + threadIdx.x;
    if (t >= BATCHG*LINW) return;
    float s = 0.f;
#pragma unroll
    for (int p = 0; p < KSPLIT; p++) s += g_G1p[(size_t)p*BATCHG*LINW + t];
    g_G1[t] = s;
}

// ---------------- SIMT fp32 GEMM for Wh2 (small) ----------------
__global__ void gemm_s(const float* __restrict__ A, const float* __restrict__ B,
                       float* __restrict__ C, int N, int K, int lda, int ldb, int ldc)
{
    __shared__ float As[16][68];
    __shared__ float Bs[16][64];
    int t = threadIdx.x;
    int m0 = blockIdx.y * 64, n0 = blockIdx.x * 64;
    int ty = t >> 4, tx = t & 15;
    int am = t >> 2, ak = (t & 3) * 4;
    int bk = t >> 4, bn = (t & 15) * 4;
    float acc[4][4];
#pragma unroll
    for (int i = 0; i < 4; i++)
#pragma unroll
        for (int j = 0; j < 4; j++) acc[i][j] = 0.f;
    for (int k0 = 0; k0 < K; k0 += 16) {
        float4 av = *reinterpret_cast<const float4*>(A + (size_t)(m0+am)*lda + k0 + ak);
        As[ak+0][am] = av.x; As[ak+1][am] = av.y; As[ak+2][am] = av.z; As[ak+3][am] = av.w;
        float4 bv = *reinterpret_cast<const float4*>(B + (size_t)(k0+bk)*ldb + n0 + bn);
        *reinterpret_cast<float4*>(&Bs[bk][bn]) = bv;
        __syncthreads();
#pragma unroll
        for (int k = 0; k < 16; k++) {
            float4 a4 = *reinterpret_cast<const float4*>(&As[k][ty*4]);
            float4 b4 = *reinterpret_cast<const float4*>(&Bs[k][tx*4]);
            float a[4] = {a4.x, a4.y, a4.z, a4.w};
            float b[4] = {b4.x, b4.y, b4.z, b4.w};
#pragma unroll
            for (int i = 0; i < 4; i++)
#pragma unroll
                for (int j = 0; j < 4; j++) acc[i][j] += a[i]*b[j];
        }
        __syncthreads();
    }
#pragma unroll
    for (int i = 0; i < 4; i++) {
        float4 v = make_float4(acc[i][0], acc[i][1], acc[i][2], acc[i][3]);
        *reinterpret_cast<float4*>(C + (size_t)(m0 + ty*4 + i)*ldc + n0 + tx*4) = v;
    }
}

// ---------------- batchnorm / final ----------------
__global__ void k_bnstats(const float* __restrict__ X, int ld){
    int c = blockIdx.x;
    int t = threadIdx.x;
    float s = 0.f, sq = 0.f;
    for (int r = t; r < BATCHG; r += 256) {
        float v = X[(size_t)r*ld + c];
        s += v; sq += v*v;
    }
    __shared__ float sh[256], sh2[256];
    sh[t] = s; sh2[t] = sq; __syncthreads();
    for (int o = 128; o > 0; o >>= 1) {
        if (t < o) { sh[t] += sh[t+o]; sh2[t] += sh2[t+o]; }
        __syncthreads();
    }
    if (t == 0) {
        float m = sh[0] * (1.f/BATCHG);
        float v = sh2[0] * (1.f/BATCHG) - m*m;
        g_mean[c] = m;
        g_rstd[c] = rsqrtf(v + 1e-5f);
    }
}
__global__ void k_bnrelu(float* __restrict__ X, int nc,
                         const float* __restrict__ gamma, const float* __restrict__ beta){
    int idx = blockIdx.x*256 + threadIdx.x;
    if (idx >= BATCHG*nc) return;
    int c = idx % nc;
    float v = X[idx];
    v = (v - g_mean[c]) * g_rstd[c] * gamma[c] + beta[c];
    X[idx] = fmaxf(v, 0.f);
}
__global__ void k_final(const float* __restrict__ Wh3, const float* __restrict__ bh3,
                        float* __restrict__ out){
    int r = blockIdx.x*256 + threadIdx.x;
    if (r >= BATCHG) return;
    const float* h = g_G2 + (size_t)r * LIN2;
    float a0 = bh3[0], a1 = bh3[1], a2 = bh3[2];
    for (int k = 0; k < LIN2; k++) {
        float v = h[k];
        a0 += v * Wh3[k*3+0];
        a1 += v * Wh3[k*3+1];
        a2 += v * Wh3[k*3+2];
    }
    float mx = fmaxf(a0, fmaxf(a1, a2));
    float e0 = expf(a0-mx), e1 = expf(a1-mx), e2 = expf(a2-mx);
    float inv = 1.f / (e0+e1+e2);
    out[r*3+0] = e0*inv; out[r*3+1] = e1*inv; out[r*3+2] = e2*inv;
}

// ---------------- launch ----------------
extern "C" void kernel_launch(void* const* d_in, const int* in_sizes, int n_in,
                              void* d_out, int out_size) {
    const float* x   = (const float*)d_in[0];
    const int*   ei  = (const int*)  d_in[1];
    const float* W[4]  = {(const float*)d_in[2], (const float*)d_in[4],
                          (const float*)d_in[6], (const float*)d_in[8]};
    const float* bb[4] = {(const float*)d_in[3], (const float*)d_in[5],
                          (const float*)d_in[7], (const float*)d_in[9]};
    const float* Wh1 = (const float*)d_in[10];
    const float* g1  = (const float*)d_in[12];
    const float* be1 = (const float*)d_in[13];
    const float* Wh2 = (const float*)d_in[14];
    const float* g2  = (const float*)d_in[16];
    const float* be2 = (const float*)d_in[17];
    const float* Wh3 = (const float*)d_in[18];
    const float* bh3 = (const float*)d_in[19];
    float* out = (float*)d_out;

    int E = in_sizes[1] / 2;
    const int* row = ei;
    const int* col = ei + E;

    float *hG1, *hG2;
    cudaGetSymbolAddress((void**)&hG1, g_G1);
    cudaGetSymbolAddress((void**)&hG2, g_G2);

    cudaFuncSetAttribute(mm_cheb,  cudaFuncAttributeMaxDynamicSharedMemorySize, CH_SMEM);
    cudaFuncSetAttribute(mm_feats, cudaFuncAttributeMaxDynamicSharedMemorySize, FT_SMEM);

    const int DPAD[4]  = {128, 192, 256, 320};
    const int DREAL[4] = {128, 190, 252, 314};

    // init H + Laplacian
    {
        size_t total = (size_t)NN*16;
        k_init_H<<<(unsigned)((total + 255)/256), 256>>>(x);
    }
    k_deg<<<1, 512>>>(row);
    k_build_L<<<1, 512>>>(row, col);
    k_L2<<<16, 256>>>();
    k_prepLA<<<32, 256>>>();

    // weight prep
    for (int i = 0; i < 4; i++) {
        int n = DPAD[i]*192;
        k_prepWt<<<(n+255)/256, 256>>>(W[i], DREAL[i], DPAD[i], i);
    }
    k_prepWh1t<<<(248*512*8 + 255)/256, 256>>>(Wh1);

    // 4 cheb layers (GEMM + fused MMA combine)
    for (int i = 0; i < 4; i++)
        mm_cheb<<<1024, 256, CH_SMEM>>>(i, DPAD[i], bb[i], 128 + 64*i);

    // MLP head
    mm_feats<<<dim3(4, 16, KSPLIT), 256, FT_SMEM>>>();
    k_reduceK<<<(BATCHG*LINW + 255)/256, 256>>>();
    k_bnstats<<<LINW, 256>>>(hG1, LINW);
    k_bnrelu<<<(BATCHG*LINW + 255)/256, 256>>>(hG1, LINW, g1, be1);

    gemm_s<<<dim3(LIN2/64, BATCHG/64), 256>>>(hG1, Wh2, hG2, LIN2, LINW, LINW, LIN2, LIN2);
    k_bnstats<<<LIN2, 256>>>(hG2, LIN2);
    k_bnrelu<<<(BATCHG*LIN2 + 255)/256, 256>>>(hG2, LIN2, g2, be2);

    k_final<<<(BATCHG + 255)/256, 256>>>(Wh3, bh3, out);
}